// round 15
// baseline (speedup 1.0000x reference)
#include <cuda_runtime.h>
#include <cuda_bf16.h>
#include <cuda_fp16.h>
#include <math.h>
#include <stdint.h>

// Problem constants
#define BATCH 4
#define HH 56
#define WW 56
#define CC 256
#define NHEAD 8
#define HD 32
#define KS 7
#define PADR 3
#define M_TOTAL (BATCH * HH * WW)   // 12544
#define QKV_N (3 * CC)              // 768
#define GK 256                      // K of both GEMMs

// Scratch (device globals: allocation-free rule)
__device__ float  g_qkv[M_TOTAL * QKV_N];    // [pix][768] q|k|v, q pre-scaled
__device__ __half g_attnh[M_TOTAL * CC];     // attention out [M][C], fp16
__device__ __half g_xh[M_TOTAL * CC];        // x, fp16
__device__ __half g_wqh[QKV_N * CC];         // w_qkv^T [768][256], fp16
__device__ __half g_wph[CC * CC];            // w_proj^T [256][256], fp16

__device__ __forceinline__ uint32_t smem_u32(const void* p) {
    uint32_t a;
    asm("{ .reg .u64 t; cvta.to.shared.u64 t, %1; cvt.u32.u64 %0, t; }"
        : "=r"(a) : "l"(p));
    return a;
}
__device__ __forceinline__ void cp16(uint32_t dst, const void* src) {
    asm volatile("cp.async.cg.shared.global [%0], [%1], 16;\n"
                 :: "r"(dst), "l"(src));
}
#define CP_COMMIT() asm volatile("cp.async.commit_group;\n" ::: "memory")
#define CP_WAIT2()  asm volatile("cp.async.wait_group 2;\n" ::: "memory")

__device__ __forceinline__ unsigned h2u(__half2 h) {
    return *reinterpret_cast<unsigned*>(&h);
}
__device__ __forceinline__ __half2 u2h(unsigned u) {
    return *reinterpret_cast<__half2*>(&u);
}

// ---------------------------------------------------------------------------
// Prep kernels: x -> fp16; weights -> transposed [N][K] fp16
// ---------------------------------------------------------------------------
__global__ void f32_to_f16(const float4* __restrict__ in,
                           __half* __restrict__ out, int n4)
{
    const int i = blockIdx.x * 256 + threadIdx.x;
    if (i < n4) {
        const float4 v = in[i];
        uint2 o;
        o.x = h2u(__floats2half2_rn(v.x, v.y));
        o.y = h2u(__floats2half2_rn(v.z, v.w));
        *(uint2*)(out + 4 * i) = o;
    }
}

// in [K][N] f32 -> out [N][K] f16
__global__ void transpose_h(const float* __restrict__ in,
                            __half* __restrict__ out, int K, int N)
{
    __shared__ float tile[32][33];
    const int n0 = blockIdx.x * 32, k0 = blockIdx.y * 32;
    for (int i = threadIdx.y; i < 32; i += 8)
        tile[i][threadIdx.x] = in[(size_t)(k0 + i) * N + n0 + threadIdx.x];
    __syncthreads();
    for (int i = threadIdx.y; i < 32; i += 8)
        out[(size_t)(n0 + i) * K + k0 + threadIdx.x] =
            __float2half_rn(tile[threadIdx.x][i]);
}

// ---------------------------------------------------------------------------
// cp.async 4-stage FP16 GEMM, 512 threads: C[M][N] = A @ Bt^T + bias.
// A [M][K=256] fp16 row-major, Bt [N][K=256] fp16 row-major.
// Block tile 128x128x32, 16 warps (4Mx4N), warp tile 32x32,
// mma.m16n8k16.f32.f16.f16.f32. Smem pitch 40 halfs (bank 20*qr+t,
// conflict-free). 4 stages = 80KB, 2 blocks/SM (32 warps), 3-tile lookahead.
// 1 cp.async per thread per tile for A and for B.
// ---------------------------------------------------------------------------
#define NSTAGE 4
#define PITCH_H 40                     // halfs per row (32 + 8 pad)
#define ASTG_B (128 * PITCH_H * 2)     // 10240
#define BSTG_B (128 * PITCH_H * 2)     // 10240
#define STG_B  (ASTG_B + BSTG_B)       // 20480
#define GEMM_SMEM (NSTAGE * STG_B)     // 81920

__device__ __forceinline__ void mma_f16(float4& d,
    unsigned a0, unsigned a1, unsigned a2, unsigned a3,
    unsigned b0, unsigned b1)
{
    asm volatile(
        "mma.sync.aligned.m16n8k16.row.col.f32.f16.f16.f32 "
        "{%0,%1,%2,%3},{%4,%5,%6,%7},{%8,%9},{%0,%1,%2,%3};\n"
        : "+f"(d.x), "+f"(d.y), "+f"(d.z), "+f"(d.w)
        : "r"(a0), "r"(a1), "r"(a2), "r"(a3), "r"(b0), "r"(b1));
}

__global__ __launch_bounds__(512, 2) void tgemm_h(
    const __half* __restrict__ A, const __half* __restrict__ Bt,
    const float* __restrict__ bias, float* __restrict__ C,
    int N, int scaleCols, float scale)
{
    extern __shared__ float sm[];
    const uint32_t sb = smem_u32(sm);
    __half* smh = (__half*)sm;
    const int tid  = threadIdx.x;
    const int wid  = tid >> 5;
    const int lane = tid & 31;
    const int warp_m = wid & 3;        // 4 warps along M (32 rows)
    const int warp_n = wid >> 2;       // 4 warps along N (32 cols)
    const int t  = lane & 3;
    const int qr = lane >> 2;
    const int bm = blockIdx.y << 7;
    const int bn = blockIdx.x << 7;

    // load mapping: row lr = tid>>2 (0..127), chunk lc = tid&3 (8 halfs)
    const int lr = tid >> 2;
    const int lc = tid & 3;
    const __half* Asrc = A + (size_t)(bm + lr) * GK + lc * 8;
    const __half* Bsrc = Bt + (size_t)(bn + lr) * GK + lc * 8;
    const uint32_t aOff = (uint32_t)(lr * PITCH_H + lc * 8) * 2u;
    const uint32_t bOff = (uint32_t)ASTG_B + aOff;

    float acc[2][4][4];
    #pragma unroll
    for (int mt = 0; mt < 2; ++mt)
        #pragma unroll
        for (int nt = 0; nt < 4; ++nt)
            #pragma unroll
            for (int i = 0; i < 4; ++i) acc[mt][nt][i] = 0.f;

    // prologue: stages 0..2 <- k-tiles 0..2
    #pragma unroll
    for (int s = 0; s < NSTAGE - 1; ++s) {
        const uint32_t sd = sb + s * STG_B;
        cp16(sd + aOff, Asrc + s * 32);
        cp16(sd + bOff, Bsrc + s * 32);
        CP_COMMIT();
    }

    #pragma unroll 1
    for (int kt = 0; kt < 8; ++kt) {
        CP_WAIT2();          // <=2 pending groups -> tile kt resident
        __syncthreads();

        if (kt + 3 < 8) {
            const uint32_t sd = sb + ((kt + 3) & 3) * STG_B;
            cp16(sd + aOff, Asrc + (kt + 3) * 32);
            cp16(sd + bOff, Bsrc + (kt + 3) * 32);
        }
        CP_COMMIT();         // always commit (keeps wait_group arithmetic exact)

        const __half* as = smh + (kt & 3) * (STG_B / 2)
                         + (warp_m * 32) * PITCH_H;
        const __half* bs = smh + (kt & 3) * (STG_B / 2) + (ASTG_B / 2)
                         + (warp_n * 32) * PITCH_H;
        #pragma unroll
        for (int ks = 0; ks < 2; ++ks) {
            const __half* ap = as + ks * 16 + 2 * t;
            const __half* bp = bs + ks * 16 + 2 * t;
            unsigned a0[2], a1[2], a2[2], a3[2];
            #pragma unroll
            for (int mt = 0; mt < 2; ++mt) {
                const __half* r0 = ap + (mt * 16 + qr) * PITCH_H;
                const __half* r1 = ap + (mt * 16 + qr + 8) * PITCH_H;
                a0[mt] = *(const unsigned*)r0;
                a1[mt] = *(const unsigned*)r1;
                a2[mt] = *(const unsigned*)(r0 + 8);
                a3[mt] = *(const unsigned*)(r1 + 8);
            }
            unsigned b0[4], b1[4];
            #pragma unroll
            for (int nt = 0; nt < 4; ++nt) {
                const __half* rn = bp + (nt * 8 + qr) * PITCH_H;
                b0[nt] = *(const unsigned*)rn;
                b1[nt] = *(const unsigned*)(rn + 8);
            }
            #pragma unroll
            for (int mt = 0; mt < 2; ++mt)
                #pragma unroll
                for (int nt = 0; nt < 4; ++nt)
                    mma_f16(*(float4*)acc[mt][nt],
                            a0[mt], a1[mt], a2[mt], a3[mt],
                            b0[nt], b1[nt]);
        }
    }

    const float sc = (bn < scaleCols) ? scale : 1.f;
    #pragma unroll
    for (int nt = 0; nt < 4; ++nt) {
        const int gn = bn + warp_n * 32 + nt * 8 + 2 * t;
        const float2 bz = *(const float2*)&bias[gn];
        #pragma unroll
        for (int mt = 0; mt < 2; ++mt) {
            const int gm = bm + warp_m * 32 + mt * 16 + qr;
            float2 r0, r1;
            r0.x = (acc[mt][nt][0] + bz.x) * sc;
            r0.y = (acc[mt][nt][1] + bz.y) * sc;
            r1.x = (acc[mt][nt][2] + bz.x) * sc;
            r1.y = (acc[mt][nt][3] + bz.y) * sc;
            *(float2*)&C[(size_t)gm * N + gn] = r0;
            *(float2*)&C[(size_t)(gm + 8) * N + gn] = r1;
        }
    }
}

// ---------------------------------------------------------------------------
// Neighborhood attention: fp16 k (HFMA2 QK) + fp32 v (proven R8 AV layout,
// no cvt in the AV loop). fp32 softmax. fp16 output for the proj GEMM.
// ---------------------------------------------------------------------------
#define TQ 8
#define WIN 14
#define KPH 56                        // halfs per k row (32 data + 24 pad)
#define K_BYTES (196 * 112)           // 21952
#define KP 36                         // floats per v row (32 + 4 pad)
#define V_BYTES (196 * KP * 4)        // 28224
#define ATTN_SMEM_BYTES (K_BYTES + V_BYTES + 256)   // 50432

__global__ __launch_bounds__(256) void na2d_attn(
    const float* __restrict__ qkv, const float* __restrict__ rpb,
    __half* __restrict__ out)
{
    extern __shared__ float sm[];
    __half* ks_h = (__half*)sm;
    float*  vs_  = (float*)((char*)sm + K_BYTES);
    float*  rpbs = (float*)((char*)sm + K_BYTES + V_BYTES);

    const int b    = blockIdx.z;
    const int head = blockIdx.y;
    const int tY   = blockIdx.x / 7;
    const int tX   = blockIdx.x - tY * 7;
    const int oy   = tY * TQ;
    const int ox   = tX * TQ;
    const int tid  = threadIdx.x;

    if (tid < 49) rpbs[tid] = rpb[head * 49 + tid];

    const bool interior = (tY >= 1) && (tY <= 5) && (tX >= 1) && (tX <= 5);
    #pragma unroll 1
    for (int idx = tid; idx < 196 * 4; idx += 256) {
        const int row = idx >> 2;
        const int c   = idx & 3;
        const int wy = row / WIN, wx = row - wy * WIN;
        const int gy = oy - PADR + wy, gx = ox - PADR + wx;
        uint4 kk = make_uint4(0, 0, 0, 0);
        float4 v0 = make_float4(0.f, 0.f, 0.f, 0.f);
        float4 v1 = make_float4(0.f, 0.f, 0.f, 0.f);
        if (interior || (gy >= 0 && gy < HH && gx >= 0 && gx < WW)) {
            const float* p = qkv + (size_t)(((b * HH + gy) * WW) + gx) * QKV_N
                           + head * HD + c * 8;
            const float4 k0 = *(const float4*)(p + 256);
            const float4 k1 = *(const float4*)(p + 260);
            v0 = *(const float4*)(p + 512);
            v1 = *(const float4*)(p + 516);
            kk.x = h2u(__floats2half2_rn(k0.x, k0.y));
            kk.y = h2u(__floats2half2_rn(k0.z, k0.w));
            kk.z = h2u(__floats2half2_rn(k1.x, k1.y));
            kk.w = h2u(__floats2half2_rn(k1.z, k1.w));
        }
        *(uint4*)(ks_h + row * KPH + c * 8) = kk;
        *(float4*)&vs_[row * KP + c * 8] = v0;
        *(float4*)&vs_[row * KP + c * 8 + 4] = v1;
    }

    const int qi = tid >> 2;
    const int g  = tid & 3;
    const int qy = qi >> 3, qx = qi & 7;
    const size_t qpix = (size_t)((b * HH + oy + qy) * WW) + ox + qx;
    const float4* qp = (const float4*)(qkv + qpix * QKV_N + head * HD);
    __half2 qh[16];
    #pragma unroll
    for (int cc = 0; cc < 8; ++cc) {
        const float4 qf = qp[cc];
        qh[2 * cc]     = __floats2half2_rn(qf.x, qf.y);
        qh[2 * cc + 1] = __floats2half2_rn(qf.z, qf.w);
    }

    __syncthreads();

    // --- phase 1: scores via HFMA2, 4 independent half2 chains ---
    float sv[13];
    #pragma unroll
    for (int u = 0; u < 13; ++u) {
        const int j = g + 4 * u;
        const bool act = (j < 49);
        const int jc = act ? j : 48;
        const int di = jc / 7, dj = jc - di * 7;
        const int row = (qy + di) * WIN + qx + dj;
        const uint4* kr = (const uint4*)(ks_h + row * KPH);
        const uint4 k0 = kr[0], k1 = kr[1], k2 = kr[2], k3 = kr[3];
        __half2 c0 = __hmul2(qh[0],  u2h(k0.x));
        __half2 c1 = __hmul2(qh[1],  u2h(k0.y));
        __half2 c2 = __hmul2(qh[2],  u2h(k0.z));
        __half2 c3 = __hmul2(qh[3],  u2h(k0.w));
        c0 = __hfma2(qh[4],  u2h(k1.x), c0);
        c1 = __hfma2(qh[5],  u2h(k1.y), c1);
        c2 = __hfma2(qh[6],  u2h(k1.z), c2);
        c3 = __hfma2(qh[7],  u2h(k1.w), c3);
        c0 = __hfma2(qh[8],  u2h(k2.x), c0);
        c1 = __hfma2(qh[9],  u2h(k2.y), c1);
        c2 = __hfma2(qh[10], u2h(k2.z), c2);
        c3 = __hfma2(qh[11], u2h(k2.w), c3);
        c0 = __hfma2(qh[12], u2h(k3.x), c0);
        c1 = __hfma2(qh[13], u2h(k3.y), c1);
        c2 = __hfma2(qh[14], u2h(k3.z), c2);
        c3 = __hfma2(qh[15], u2h(k3.w), c3);
        const __half2 r = __hadd2(__hadd2(c0, c1), __hadd2(c2, c3));
        const float2 f = __half22float2(r);
        sv[u] = act ? (f.x + f.y + rpbs[jc]) : -1e30f;
    }

    // --- softmax across quad (fp32) ---
    float m = sv[0];
    #pragma unroll
    for (int u = 1; u < 13; ++u) m = fmaxf(m, sv[u]);
    m = fmaxf(m, __shfl_xor_sync(0xffffffffu, m, 1));
    m = fmaxf(m, __shfl_xor_sync(0xffffffffu, m, 2));
    float ssum = 0.f;
    #pragma unroll
    for (int u = 0; u < 13; ++u) {
        const float e = __expf(sv[u] - m);
        sv[u] = e;
        ssum += e;
    }
    ssum += __shfl_xor_sync(0xffffffffu, ssum, 1);
    ssum += __shfl_xor_sync(0xffffffffu, ssum, 2);
    const float inv = 1.f / ssum;
    #pragma unroll
    for (int u = 0; u < 13; ++u) sv[u] *= inv;

    // --- phase 3: AV (fp32 v, proven R8 layout; no cvt in loop) ---
    const int lanebase = (tid & 31) & ~3;
    float4 a0 = make_float4(0.f, 0.f, 0.f, 0.f);
    float4 a1 = make_float4(0.f, 0.f, 0.f, 0.f);
    #pragma unroll
    for (int di = 0; di < 7; ++di) {
        const float* vrow = vs_ + ((qy + di) * WIN + qx) * KP + g * 8;
        #pragma unroll
        for (int dj = 0; dj < 7; ++dj) {
            const int j = di * 7 + dj;
            const float w = __shfl_sync(0xffffffffu, sv[j >> 2],
                                        lanebase | (j & 3));
            const float4 v0 = *(const float4*)(vrow + dj * KP);
            const float4 v1 = *(const float4*)(vrow + dj * KP + 4);
            a0.x = fmaf(w, v0.x, a0.x); a0.y = fmaf(w, v0.y, a0.y);
            a0.z = fmaf(w, v0.z, a0.z); a0.w = fmaf(w, v0.w, a0.w);
            a1.x = fmaf(w, v1.x, a1.x); a1.y = fmaf(w, v1.y, a1.y);
            a1.z = fmaf(w, v1.z, a1.z); a1.w = fmaf(w, v1.w, a1.w);
        }
    }
    // fp16 output (proj GEMM A operand)
    uint4 o;
    o.x = h2u(__floats2half2_rn(a0.x, a0.y));
    o.y = h2u(__floats2half2_rn(a0.z, a0.w));
    o.z = h2u(__floats2half2_rn(a1.x, a1.y));
    o.w = h2u(__floats2half2_rn(a1.z, a1.w));
    *(uint4*)(out + qpix * CC + head * HD + g * 8) = o;
}

// ---------------------------------------------------------------------------
extern "C" void kernel_launch(void* const* d_in, const int* in_sizes, int n_in,
                              void* d_out, int out_size)
{
    (void)in_sizes; (void)n_in; (void)out_size;
    const float* x      = (const float*)d_in[0];
    const float* w_qkv  = (const float*)d_in[1];
    const float* b_qkv  = (const float*)d_in[2];
    const float* rpb    = (const float*)d_in[3];
    const float* w_proj = (const float*)d_in[4];
    const float* b_proj = (const float*)d_in[5];
    float* out = (float*)d_out;

    float* qkvb = nullptr;
    __half *attnh = nullptr, *xh = nullptr, *wqh = nullptr, *wph = nullptr;
    cudaGetSymbolAddress((void**)&qkvb, g_qkv);
    cudaGetSymbolAddress((void**)&attnh, g_attnh);
    cudaGetSymbolAddress((void**)&xh, g_xh);
    cudaGetSymbolAddress((void**)&wqh, g_wqh);
    cudaGetSymbolAddress((void**)&wph, g_wph);

    cudaFuncSetAttribute(tgemm_h, cudaFuncAttributeMaxDynamicSharedMemorySize,
                         GEMM_SMEM);
    cudaFuncSetAttribute(na2d_attn, cudaFuncAttributeMaxDynamicSharedMemorySize,
                         ATTN_SMEM_BYTES);

    const float qscale = 0.17677669529663689f; // 32^-0.5

    // 0) prep: x -> fp16; weights -> transposed [N][K] fp16
    {
        const int nx = M_TOTAL * CC / 4;
        f32_to_f16<<<(nx + 255) / 256, 256>>>((const float4*)x, xh, nx);
        transpose_h<<<dim3(QKV_N / 32, CC / 32), dim3(32, 8)>>>(w_qkv, wqh, CC, QKV_N);
        transpose_h<<<dim3(CC / 32, CC / 32), dim3(32, 8)>>>(w_proj, wph, CC, CC);
    }

    // 1) qkv = x @ w_qkv + b_qkv  (q columns pre-scaled)
    tgemm_h<<<dim3(QKV_N / 128, M_TOTAL / 128), 512, GEMM_SMEM>>>(
        xh, wqh, b_qkv, qkvb, QKV_N, 256, qscale);

    // 2) neighborhood attention (fp16 output for proj GEMM)
    na2d_attn<<<dim3(49, NHEAD, BATCH), 256, ATTN_SMEM_BYTES>>>(qkvb, rpb, attnh);

    // 3) out = attn @ w_proj + b_proj
    tgemm_h<<<dim3(CC / 128, M_TOTAL / 128), 512, GEMM_SMEM>>>(
        attnh, wph, b_proj, out, CC, 0, 1.f);
}

// round 16
// speedup vs baseline: 1.0951x; 1.0951x over previous
#include <cuda_runtime.h>
#include <cuda_bf16.h>
#include <cuda_fp16.h>
#include <math.h>
#include <stdint.h>

// Problem constants
#define BATCH 4
#define HH 56
#define WW 56
#define CC 256
#define NHEAD 8
#define HD 32
#define KS 7
#define PADR 3
#define M_TOTAL (BATCH * HH * WW)   // 12544
#define QKV_N (3 * CC)              // 768
#define GK 256                      // K of both GEMMs

// Scratch (device globals: allocation-free rule)
__device__ __half g_qkvh[M_TOTAL * QKV_N];   // [pix][768] q|k|v fp16, q pre-scaled
__device__ __half g_attnh[M_TOTAL * CC];     // attention out [M][C], fp16
__device__ __half g_xh[M_TOTAL * CC];        // x, fp16
__device__ __half g_wqh[QKV_N * CC];         // w_qkv^T [768][256], fp16
__device__ __half g_wph[CC * CC];            // w_proj^T [256][256], fp16

__device__ __forceinline__ uint32_t smem_u32(const void* p) {
    uint32_t a;
    asm("{ .reg .u64 t; cvta.to.shared.u64 t, %1; cvt.u32.u64 %0, t; }"
        : "=r"(a) : "l"(p));
    return a;
}
__device__ __forceinline__ void cp16(uint32_t dst, const void* src) {
    asm volatile("cp.async.cg.shared.global [%0], [%1], 16;\n"
                 :: "r"(dst), "l"(src));
}
// zero-fill variant: copies `size` bytes (0 or 16), zero-fills the rest
__device__ __forceinline__ void cp16z(uint32_t dst, const void* src, unsigned size) {
    asm volatile("cp.async.cg.shared.global [%0], [%1], 16, %2;\n"
                 :: "r"(dst), "l"(src), "r"(size));
}
#define CP_COMMIT() asm volatile("cp.async.commit_group;\n" ::: "memory")
#define CP_WAIT2()  asm volatile("cp.async.wait_group 2;\n" ::: "memory")
#define CP_WAIT0()  asm volatile("cp.async.wait_group 0;\n" ::: "memory")

__device__ __forceinline__ unsigned h2u(__half2 h) {
    return *reinterpret_cast<unsigned*>(&h);
}
__device__ __forceinline__ __half2 u2h(unsigned u) {
    return *reinterpret_cast<__half2*>(&u);
}

// ---------------------------------------------------------------------------
// Prep kernels: x -> fp16; weights -> transposed [N][K] fp16
// ---------------------------------------------------------------------------
__global__ void f32_to_f16(const float4* __restrict__ in,
                           __half* __restrict__ out, int n4)
{
    const int i = blockIdx.x * 256 + threadIdx.x;
    if (i < n4) {
        const float4 v = in[i];
        uint2 o;
        o.x = h2u(__floats2half2_rn(v.x, v.y));
        o.y = h2u(__floats2half2_rn(v.z, v.w));
        *(uint2*)(out + 4 * i) = o;
    }
}

// in [K][N] f32 -> out [N][K] f16
__global__ void transpose_h(const float* __restrict__ in,
                            __half* __restrict__ out, int K, int N)
{
    __shared__ float tile[32][33];
    const int n0 = blockIdx.x * 32, k0 = blockIdx.y * 32;
    for (int i = threadIdx.y; i < 32; i += 8)
        tile[i][threadIdx.x] = in[(size_t)(k0 + i) * N + n0 + threadIdx.x];
    __syncthreads();
    for (int i = threadIdx.y; i < 32; i += 8)
        out[(size_t)(n0 + i) * K + k0 + threadIdx.x] =
            __float2half_rn(tile[threadIdx.x][i]);
}

// ---------------------------------------------------------------------------
// cp.async 4-stage FP16 GEMM (round-14 proven config: 256 thr, 8 warps 4Mx2N,
// warp tile 32x64, mma.m16n8k16, pitch 40, 3-tile lookahead, 2 blocks/SM).
// HALF_OUT=true -> writes fp16 C; false -> fp32 C.
// ---------------------------------------------------------------------------
#define NSTAGE 4
#define PITCH_H 40                     // halfs per row (32 + 8 pad)
#define ASTG_B (128 * PITCH_H * 2)     // 10240
#define BSTG_B (128 * PITCH_H * 2)     // 10240
#define STG_B  (ASTG_B + BSTG_B)       // 20480
#define GEMM_SMEM (NSTAGE * STG_B)     // 81920

__device__ __forceinline__ void mma_f16(float4& d,
    unsigned a0, unsigned a1, unsigned a2, unsigned a3,
    unsigned b0, unsigned b1)
{
    asm volatile(
        "mma.sync.aligned.m16n8k16.row.col.f32.f16.f16.f32 "
        "{%0,%1,%2,%3},{%4,%5,%6,%7},{%8,%9},{%0,%1,%2,%3};\n"
        : "+f"(d.x), "+f"(d.y), "+f"(d.z), "+f"(d.w)
        : "r"(a0), "r"(a1), "r"(a2), "r"(a3), "r"(b0), "r"(b1));
}

template <bool HALF_OUT>
__global__ __launch_bounds__(256, 2) void tgemm_h(
    const __half* __restrict__ A, const __half* __restrict__ Bt,
    const float* __restrict__ bias, void* __restrict__ Cv,
    int N, int scaleCols, float scale)
{
    extern __shared__ float sm[];
    const uint32_t sb = smem_u32(sm);
    __half* smh = (__half*)sm;
    const int tid  = threadIdx.x;
    const int wid  = tid >> 5;
    const int lane = tid & 31;
    const int warp_m = wid & 3;        // 4 warps along M (32 rows)
    const int warp_n = wid >> 2;       // 2 warps along N (64 cols)
    const int t  = lane & 3;
    const int qr = lane >> 2;
    const int bm = blockIdx.y << 7;
    const int bn = blockIdx.x << 7;

    const int lr = tid >> 2;           // 0..63
    const int lc = tid & 3;
    const __half* Asrc = A + (size_t)(bm + lr) * GK + lc * 8;
    const __half* Bsrc = Bt + (size_t)(bn + lr) * GK + lc * 8;
    const uint32_t aOff = (uint32_t)(lr * PITCH_H + lc * 8) * 2u;
    const uint32_t bOff = (uint32_t)ASTG_B + aOff;
    const uint32_t rowStep = 64u * PITCH_H * 2u;

    float acc[2][8][4];
    #pragma unroll
    for (int mt = 0; mt < 2; ++mt)
        #pragma unroll
        for (int nt = 0; nt < 8; ++nt)
            #pragma unroll
            for (int i = 0; i < 4; ++i) acc[mt][nt][i] = 0.f;

    #pragma unroll
    for (int s = 0; s < NSTAGE - 1; ++s) {
        const uint32_t sd = sb + s * STG_B;
        cp16(sd + aOff, Asrc + s * 32);
        cp16(sd + aOff + rowStep, Asrc + (size_t)64 * GK + s * 32);
        cp16(sd + bOff, Bsrc + s * 32);
        cp16(sd + bOff + rowStep, Bsrc + (size_t)64 * GK + s * 32);
        CP_COMMIT();
    }

    #pragma unroll 1
    for (int kt = 0; kt < 8; ++kt) {
        CP_WAIT2();
        __syncthreads();

        if (kt + 3 < 8) {
            const uint32_t sd = sb + ((kt + 3) & 3) * STG_B;
            cp16(sd + aOff, Asrc + (kt + 3) * 32);
            cp16(sd + aOff + rowStep, Asrc + (size_t)64 * GK + (kt + 3) * 32);
            cp16(sd + bOff, Bsrc + (kt + 3) * 32);
            cp16(sd + bOff + rowStep, Bsrc + (size_t)64 * GK + (kt + 3) * 32);
        }
        CP_COMMIT();

        const __half* as = smh + (kt & 3) * (STG_B / 2)
                         + (warp_m * 32) * PITCH_H;
        const __half* bs = smh + (kt & 3) * (STG_B / 2) + (ASTG_B / 2)
                         + (warp_n * 64) * PITCH_H;
        #pragma unroll
        for (int ks = 0; ks < 2; ++ks) {
            const __half* ap = as + ks * 16 + 2 * t;
            const __half* bp = bs + ks * 16 + 2 * t;
            unsigned a0[2], a1[2], a2[2], a3[2];
            #pragma unroll
            for (int mt = 0; mt < 2; ++mt) {
                const __half* r0 = ap + (mt * 16 + qr) * PITCH_H;
                const __half* r1 = ap + (mt * 16 + qr + 8) * PITCH_H;
                a0[mt] = *(const unsigned*)r0;
                a1[mt] = *(const unsigned*)r1;
                a2[mt] = *(const unsigned*)(r0 + 8);
                a3[mt] = *(const unsigned*)(r1 + 8);
            }
            unsigned b0[8], b1[8];
            #pragma unroll
            for (int nt = 0; nt < 8; ++nt) {
                const __half* rn = bp + (nt * 8 + qr) * PITCH_H;
                b0[nt] = *(const unsigned*)rn;
                b1[nt] = *(const unsigned*)(rn + 8);
            }
            #pragma unroll
            for (int mt = 0; mt < 2; ++mt)
                #pragma unroll
                for (int nt = 0; nt < 8; ++nt)
                    mma_f16(*(float4*)acc[mt][nt],
                            a0[mt], a1[mt], a2[mt], a3[mt],
                            b0[nt], b1[nt]);
        }
    }

    const float sc = (bn < scaleCols) ? scale : 1.f;
    #pragma unroll
    for (int nt = 0; nt < 8; ++nt) {
        const int gn = bn + warp_n * 64 + nt * 8 + 2 * t;
        const float2 bz = *(const float2*)&bias[gn];
        #pragma unroll
        for (int mt = 0; mt < 2; ++mt) {
            const int gm = bm + warp_m * 32 + mt * 16 + qr;
            float2 r0, r1;
            r0.x = (acc[mt][nt][0] + bz.x) * sc;
            r0.y = (acc[mt][nt][1] + bz.y) * sc;
            r1.x = (acc[mt][nt][2] + bz.x) * sc;
            r1.y = (acc[mt][nt][3] + bz.y) * sc;
            if (HALF_OUT) {
                __half* Ch = (__half*)Cv;
                *(unsigned*)&Ch[(size_t)gm * N + gn] = h2u(__floats2half2_rn(r0.x, r0.y));
                *(unsigned*)&Ch[(size_t)(gm + 8) * N + gn] = h2u(__floats2half2_rn(r1.x, r1.y));
            } else {
                float* Cf = (float*)Cv;
                *(float2*)&Cf[(size_t)gm * N + gn] = r0;
                *(float2*)&Cf[(size_t)(gm + 8) * N + gn] = r1;
            }
        }
    }
}

// ---------------------------------------------------------------------------
// Neighborhood attention, all-fp16 inputs: k/v window loaded gmem->smem via
// cp.async (zero-fill for OOB, no cvt, no register staging). HFMA2 QK,
// fp32 softmax, fp32-accumulate AV over fp16 v. fp16 output.
// k: row-major pitch 56 halfs (proven R13/14); v: 4 dim planes, VPLANE=1576
// (proven conflict-free AV from R12/13).
// ---------------------------------------------------------------------------
#define TQ 8
#define WIN 14
#define KPH 56                        // halfs per k row
#define K_BYTES (196 * 112)           // 21952
#define VPLANE 1576                   // halfs per v plane
#define V_BYTES (4 * VPLANE * 2)      // 12608
#define ATTN_SMEM_BYTES (K_BYTES + V_BYTES + 256)   // 34816

__global__ __launch_bounds__(256) void na2d_attn(
    const __half* __restrict__ qkvh, const float* __restrict__ rpb,
    __half* __restrict__ out)
{
    extern __shared__ float sm[];
    __half* ks_h = (__half*)sm;
    __half* vs_h = (__half*)((char*)sm + K_BYTES);
    float*  rpbs = (float*)((char*)sm + K_BYTES + V_BYTES);

    const int b    = blockIdx.z;
    const int head = blockIdx.y;
    const int tY   = blockIdx.x / 7;
    const int tX   = blockIdx.x - tY * 7;
    const int oy   = tY * TQ;
    const int ox   = tX * TQ;
    const int tid  = threadIdx.x;
    const uint32_t smb = smem_u32(sm);

    if (tid < 49) rpbs[tid] = rpb[head * 49 + tid];

    // --- cp.async window load: 196 rows x (4 k-chunks + 4 v-chunks) ---
    const bool interior = (tY >= 1) && (tY <= 5) && (tX >= 1) && (tX <= 5);
    #pragma unroll 1
    for (int idx = tid; idx < 196 * 8; idx += 256) {
        const int row = idx >> 3;
        const int sub = idx & 7;            // 0..3 = k chunk, 4..7 = v chunk
        const int wy = row / WIN, wx = row - wy * WIN;
        const int gy = oy - PADR + wy, gx = ox - PADR + wx;
        const bool ok = interior || ((unsigned)gy < HH && (unsigned)gx < WW);
        const int kc = sub & 3;
        // dst: k -> row*112 + kc*16 ; v -> K_BYTES + kc*3152 + row*16
        const uint32_t dst = (sub < 4)
            ? smb + (uint32_t)(row * 112 + kc * 16)
            : smb + (uint32_t)(K_BYTES + kc * (VPLANE * 2) + row * 16);
        const __half* src = ok
            ? qkvh + (size_t)(((b * HH + gy) * WW) + gx) * QKV_N
                   + ((sub < 4) ? 256 : 512) + head * HD + kc * 8
            : qkvh;
        cp16z(dst, src, ok ? 16u : 0u);
    }
    CP_COMMIT();

    // --- q into fp16 half2 registers (no conversion) ---
    const int qi = tid >> 2;
    const int g  = tid & 3;
    const int qy = qi >> 3, qx = qi & 7;
    const size_t qpix = (size_t)((b * HH + oy + qy) * WW) + ox + qx;
    const uint4* qp = (const uint4*)(qkvh + qpix * QKV_N + head * HD);
    uint4 q0 = qp[0], q1 = qp[1], q2 = qp[2], q3 = qp[3];
    unsigned qh[16] = { q0.x, q0.y, q0.z, q0.w, q1.x, q1.y, q1.z, q1.w,
                        q2.x, q2.y, q2.z, q2.w, q3.x, q3.y, q3.z, q3.w };

    CP_WAIT0();
    __syncthreads();

    // --- phase 1: scores via HFMA2, 4 independent half2 chains ---
    float sv[13];
    #pragma unroll
    for (int u = 0; u < 13; ++u) {
        const int j = g + 4 * u;
        const bool act = (j < 49);
        const int jc = act ? j : 48;
        const int di = jc / 7, dj = jc - di * 7;
        const int row = (qy + di) * WIN + qx + dj;
        const uint4* kr = (const uint4*)(ks_h + row * KPH);
        const uint4 k0 = kr[0], k1 = kr[1], k2 = kr[2], k3 = kr[3];
        __half2 c0 = __hmul2(u2h(qh[0]),  u2h(k0.x));
        __half2 c1 = __hmul2(u2h(qh[1]),  u2h(k0.y));
        __half2 c2 = __hmul2(u2h(qh[2]),  u2h(k0.z));
        __half2 c3 = __hmul2(u2h(qh[3]),  u2h(k0.w));
        c0 = __hfma2(u2h(qh[4]),  u2h(k1.x), c0);
        c1 = __hfma2(u2h(qh[5]),  u2h(k1.y), c1);
        c2 = __hfma2(u2h(qh[6]),  u2h(k1.z), c2);
        c3 = __hfma2(u2h(qh[7]),  u2h(k1.w), c3);
        c0 = __hfma2(u2h(qh[8]),  u2h(k2.x), c0);
        c1 = __hfma2(u2h(qh[9]),  u2h(k2.y), c1);
        c2 = __hfma2(u2h(qh[10]), u2h(k2.z), c2);
        c3 = __hfma2(u2h(qh[11]), u2h(k2.w), c3);
        c0 = __hfma2(u2h(qh[12]), u2h(k3.x), c0);
        c1 = __hfma2(u2h(qh[13]), u2h(k3.y), c1);
        c2 = __hfma2(u2h(qh[14]), u2h(k3.z), c2);
        c3 = __hfma2(u2h(qh[15]), u2h(k3.w), c3);
        const __half2 r = __hadd2(__hadd2(c0, c1), __hadd2(c2, c3));
        const float2 f = __half22float2(r);
        sv[u] = act ? (f.x + f.y + rpbs[jc]) : -1e30f;
    }

    // --- softmax across quad (fp32) ---
    float m = sv[0];
    #pragma unroll
    for (int u = 1; u < 13; ++u) m = fmaxf(m, sv[u]);
    m = fmaxf(m, __shfl_xor_sync(0xffffffffu, m, 1));
    m = fmaxf(m, __shfl_xor_sync(0xffffffffu, m, 2));
    float ssum = 0.f;
    #pragma unroll
    for (int u = 0; u < 13; ++u) {
        const float e = __expf(sv[u] - m);
        sv[u] = e;
        ssum += e;
    }
    ssum += __shfl_xor_sync(0xffffffffu, ssum, 1);
    ssum += __shfl_xor_sync(0xffffffffu, ssum, 2);
    const float inv = 1.f / ssum;
    #pragma unroll
    for (int u = 0; u < 13; ++u) sv[u] *= inv;

    // --- phase 3: AV (fp32 accumulate over fp16 v plane g) ---
    const int lanebase = (tid & 31) & ~3;
    const __half* vbase = vs_h + g * VPLANE;
    float4 a0 = make_float4(0.f, 0.f, 0.f, 0.f);
    float4 a1 = make_float4(0.f, 0.f, 0.f, 0.f);
    #pragma unroll
    for (int di = 0; di < 7; ++di) {
        const int rbase = (qy + di) * WIN + qx;
        #pragma unroll
        for (int dj = 0; dj < 7; ++dj) {
            const int j = di * 7 + dj;
            const float w = __shfl_sync(0xffffffffu, sv[j >> 2],
                                        lanebase | (j & 3));
            const uint4 vv = *(const uint4*)(vbase + (rbase + dj) * 8);
            const float2 f0 = __half22float2(u2h(vv.x));
            const float2 f1 = __half22float2(u2h(vv.y));
            const float2 f2 = __half22float2(u2h(vv.z));
            const float2 f3 = __half22float2(u2h(vv.w));
            a0.x = fmaf(w, f0.x, a0.x); a0.y = fmaf(w, f0.y, a0.y);
            a0.z = fmaf(w, f1.x, a0.z); a0.w = fmaf(w, f1.y, a0.w);
            a1.x = fmaf(w, f2.x, a1.x); a1.y = fmaf(w, f2.y, a1.y);
            a1.z = fmaf(w, f3.x, a1.z); a1.w = fmaf(w, f3.y, a1.w);
        }
    }
    // NOTE: v plane g holds dims 8g..8g+7 -> output offset head*HD + g*8
    uint4 o;
    o.x = h2u(__floats2half2_rn(a0.x, a0.y));
    o.y = h2u(__floats2half2_rn(a0.z, a0.w));
    o.z = h2u(__floats2half2_rn(a1.x, a1.y));
    o.w = h2u(__floats2half2_rn(a1.z, a1.w));
    *(uint4*)(out + qpix * CC + head * HD + g * 8) = o;
}

// ---------------------------------------------------------------------------
extern "C" void kernel_launch(void* const* d_in, const int* in_sizes, int n_in,
                              void* d_out, int out_size)
{
    (void)in_sizes; (void)n_in; (void)out_size;
    const float* x      = (const float*)d_in[0];
    const float* w_qkv  = (const float*)d_in[1];
    const float* b_qkv  = (const float*)d_in[2];
    const float* rpb    = (const float*)d_in[3];
    const float* w_proj = (const float*)d_in[4];
    const float* b_proj = (const float*)d_in[5];
    float* out = (float*)d_out;

    __half *qkvh = nullptr, *attnh = nullptr, *xh = nullptr, *wqh = nullptr, *wph = nullptr;
    cudaGetSymbolAddress((void**)&qkvh, g_qkvh);
    cudaGetSymbolAddress((void**)&attnh, g_attnh);
    cudaGetSymbolAddress((void**)&xh, g_xh);
    cudaGetSymbolAddress((void**)&wqh, g_wqh);
    cudaGetSymbolAddress((void**)&wph, g_wph);

    cudaFuncSetAttribute(tgemm_h<true>, cudaFuncAttributeMaxDynamicSharedMemorySize,
                         GEMM_SMEM);
    cudaFuncSetAttribute(tgemm_h<false>, cudaFuncAttributeMaxDynamicSharedMemorySize,
                         GEMM_SMEM);
    cudaFuncSetAttribute(na2d_attn, cudaFuncAttributeMaxDynamicSharedMemorySize,
                         ATTN_SMEM_BYTES);

    const float qscale = 0.17677669529663689f; // 32^-0.5

    // 0) prep: x -> fp16; weights -> transposed [N][K] fp16
    {
        const int nx = M_TOTAL * CC / 4;
        f32_to_f16<<<(nx + 255) / 256, 256>>>((const float4*)x, xh, nx);
        transpose_h<<<dim3(QKV_N / 32, CC / 32), dim3(32, 8)>>>(w_qkv, wqh, CC, QKV_N);
        transpose_h<<<dim3(CC / 32, CC / 32), dim3(32, 8)>>>(w_proj, wph, CC, CC);
    }

    // 1) qkv = x @ w_qkv + b_qkv  (q cols pre-scaled; fp16 output)
    tgemm_h<true><<<dim3(QKV_N / 128, M_TOTAL / 128), 256, GEMM_SMEM>>>(
        xh, wqh, b_qkv, qkvh, QKV_N, 256, qscale);

    // 2) neighborhood attention (all-fp16 I/O)
    na2d_attn<<<dim3(49, NHEAD, BATCH), 256, ATTN_SMEM_BYTES>>>(qkvh, rpb, attnh);

    // 3) out = attn @ w_proj + b_proj (fp32 output)
    tgemm_h<false><<<dim3(CC / 128, M_TOTAL / 128), 256, GEMM_SMEM>>>(
        attnh, wph, b_proj, out, CC, 0, 1.f);
}

// round 17
// speedup vs baseline: 1.1518x; 1.0517x over previous
#include <cuda_runtime.h>
#include <cuda_bf16.h>
#include <cuda_fp16.h>
#include <math.h>
#include <stdint.h>

// Problem constants
#define BATCH 4
#define HH 56
#define WW 56
#define CC 256
#define NHEAD 8
#define HD 32
#define KS 7
#define PADR 3
#define M_TOTAL (BATCH * HH * WW)   // 12544
#define QKV_N (3 * CC)              // 768
#define GK 256                      // K of both GEMMs

// Scratch (device globals: allocation-free rule)
__device__ __half g_qkvh[M_TOTAL * QKV_N];   // [pix][768] q|k|v fp16, q pre-scaled
__device__ __half g_attnh[M_TOTAL * CC];     // attention out [M][C], fp16
__device__ __half g_xh[M_TOTAL * CC];        // x, fp16
__device__ __half g_wqh[QKV_N * CC];         // w_qkv^T [768][256], fp16
__device__ __half g_wph[CC * CC];            // w_proj^T [256][256], fp16

__device__ __forceinline__ uint32_t smem_u32(const void* p) {
    uint32_t a;
    asm("{ .reg .u64 t; cvta.to.shared.u64 t, %1; cvt.u32.u64 %0, t; }"
        : "=r"(a) : "l"(p));
    return a;
}
__device__ __forceinline__ void cp16(uint32_t dst, const void* src) {
    asm volatile("cp.async.cg.shared.global [%0], [%1], 16;\n"
                 :: "r"(dst), "l"(src));
}
__device__ __forceinline__ void cp16z(uint32_t dst, const void* src, unsigned size) {
    asm volatile("cp.async.cg.shared.global [%0], [%1], 16, %2;\n"
                 :: "r"(dst), "l"(src), "r"(size));
}
#define CP_COMMIT() asm volatile("cp.async.commit_group;\n" ::: "memory")
#define CP_WAIT1()  asm volatile("cp.async.wait_group 1;\n" ::: "memory")
#define CP_WAIT0()  asm volatile("cp.async.wait_group 0;\n" ::: "memory")

__device__ __forceinline__ unsigned h2u(__half2 h) {
    return *reinterpret_cast<unsigned*>(&h);
}
__device__ __forceinline__ __half2 u2h(unsigned u) {
    return *reinterpret_cast<__half2*>(&u);
}

// ---------------------------------------------------------------------------
// Prep kernels: x -> fp16; weights -> transposed [N][K] fp16
// ---------------------------------------------------------------------------
__global__ void f32_to_f16(const float4* __restrict__ in,
                           __half* __restrict__ out, int n4)
{
    const int i = blockIdx.x * 256 + threadIdx.x;
    if (i < n4) {
        const float4 v = in[i];
        uint2 o;
        o.x = h2u(__floats2half2_rn(v.x, v.y));
        o.y = h2u(__floats2half2_rn(v.z, v.w));
        *(uint2*)(out + 4 * i) = o;
    }
}

__global__ void transpose_h(const float* __restrict__ in,
                            __half* __restrict__ out, int K, int N)
{
    __shared__ float tile[32][33];
    const int n0 = blockIdx.x * 32, k0 = blockIdx.y * 32;
    for (int i = threadIdx.y; i < 32; i += 8)
        tile[i][threadIdx.x] = in[(size_t)(k0 + i) * N + n0 + threadIdx.x];
    __syncthreads();
    for (int i = threadIdx.y; i < 32; i += 8)
        out[(size_t)(n0 + i) * K + k0 + threadIdx.x] =
            __float2half_rn(tile[threadIdx.x][i]);
}

// ---------------------------------------------------------------------------
// cp.async 3-stage FP16 GEMM, BK=64 (4 k-tiles -> half the barrier events).
// A [M][K=256] fp16 row-major, Bt [N][K=256] fp16 row-major.
// Block tile 128x128x64, 256 thr = 8 warps (4Mx2N), warp tile 32x64,
// mma.m16n8k16. Smem pitch 72 halfs (fragment word = 4*qr+t, conflict-free).
// 3 stages = 108KB, 2 blocks/SM, 2-tile lookahead.
// ---------------------------------------------------------------------------
#define NSTAGE 3
#define BKH 64
#define PITCH_H 72                     // halfs per row (64 + 8 pad)
#define ASTG_B (128 * PITCH_H * 2)     // 18432
#define STG_B  (2 * ASTG_B)            // 36864
#define GEMM_SMEM (NSTAGE * STG_B)     // 110592

__device__ __forceinline__ void mma_f16(float4& d,
    unsigned a0, unsigned a1, unsigned a2, unsigned a3,
    unsigned b0, unsigned b1)
{
    asm volatile(
        "mma.sync.aligned.m16n8k16.row.col.f32.f16.f16.f32 "
        "{%0,%1,%2,%3},{%4,%5,%6,%7},{%8,%9},{%0,%1,%2,%3};\n"
        : "+f"(d.x), "+f"(d.y), "+f"(d.z), "+f"(d.w)
        : "r"(a0), "r"(a1), "r"(a2), "r"(a3), "r"(b0), "r"(b1));
}

template <bool HALF_OUT>
__global__ __launch_bounds__(256, 2) void tgemm_h(
    const __half* __restrict__ A, const __half* __restrict__ Bt,
    const float* __restrict__ bias, void* __restrict__ Cv,
    int N, int scaleCols, float scale)
{
    extern __shared__ float sm[];
    const uint32_t sb = smem_u32(sm);
    __half* smh = (__half*)sm;
    const int tid  = threadIdx.x;
    const int wid  = tid >> 5;
    const int lane = tid & 31;
    const int warp_m = wid & 3;        // 4 warps along M (32 rows)
    const int warp_n = wid >> 2;       // 2 warps along N (64 cols)
    const int t  = lane & 3;
    const int qr = lane >> 2;
    const int bm = blockIdx.y << 7;
    const int bn = blockIdx.x << 7;

    // flat-chunk load map: chunk c = tid + 256e -> row lr+32e, col lc (16B)
    const int lr = tid >> 3;           // 0..31
    const int lc = tid & 7;
    const __half* Asrc = A + (size_t)(bm + lr) * GK + lc * 8;
    const __half* Bsrc = Bt + (size_t)(bn + lr) * GK + lc * 8;
    const uint32_t aOff = (uint32_t)(lr * PITCH_H + lc * 8) * 2u;
    const uint32_t bOff = (uint32_t)ASTG_B + aOff;
    const uint32_t rowStep = 32u * PITCH_H * 2u;   // +32 rows in bytes

    float acc[2][8][4];
    #pragma unroll
    for (int mt = 0; mt < 2; ++mt)
        #pragma unroll
        for (int nt = 0; nt < 8; ++nt)
            #pragma unroll
            for (int i = 0; i < 4; ++i) acc[mt][nt][i] = 0.f;

    // prologue: stages 0,1 <- k-tiles 0,1
    #pragma unroll
    for (int s = 0; s < NSTAGE - 1; ++s) {
        const uint32_t sd = sb + s * STG_B;
        #pragma unroll
        for (int e = 0; e < 4; ++e) {
            cp16(sd + aOff + e * rowStep, Asrc + (size_t)e * 32 * GK + s * BKH);
            cp16(sd + bOff + e * rowStep, Bsrc + (size_t)e * 32 * GK + s * BKH);
        }
        CP_COMMIT();
    }

    int stage = 0;
    #pragma unroll 1
    for (int kt = 0; kt < 4; ++kt) {
        CP_WAIT1();          // <=1 pending group -> tile kt resident
        __syncthreads();

        if (kt + 2 < 4) {
            const int ls = (stage + 2 >= NSTAGE) ? stage + 2 - NSTAGE : stage + 2;
            const uint32_t sd = sb + ls * STG_B;
            #pragma unroll
            for (int e = 0; e < 4; ++e) {
                cp16(sd + aOff + e * rowStep, Asrc + (size_t)e * 32 * GK + (kt + 2) * BKH);
                cp16(sd + bOff + e * rowStep, Bsrc + (size_t)e * 32 * GK + (kt + 2) * BKH);
            }
        }
        CP_COMMIT();         // always commit (keeps wait_group arithmetic exact)

        const __half* as = smh + stage * (STG_B / 2) + (warp_m * 32) * PITCH_H;
        const __half* bs = smh + stage * (STG_B / 2) + (ASTG_B / 2)
                         + (warp_n * 64) * PITCH_H;
        #pragma unroll
        for (int ks = 0; ks < 4; ++ks) {
            const __half* ap = as + ks * 16 + 2 * t;
            const __half* bp = bs + ks * 16 + 2 * t;
            unsigned a0[2], a1[2], a2[2], a3[2];
            #pragma unroll
            for (int mt = 0; mt < 2; ++mt) {
                const __half* r0 = ap + (mt * 16 + qr) * PITCH_H;
                const __half* r1 = ap + (mt * 16 + qr + 8) * PITCH_H;
                a0[mt] = *(const unsigned*)r0;
                a1[mt] = *(const unsigned*)r1;
                a2[mt] = *(const unsigned*)(r0 + 8);
                a3[mt] = *(const unsigned*)(r1 + 8);
            }
            unsigned b0[8], b1[8];
            #pragma unroll
            for (int nt = 0; nt < 8; ++nt) {
                const __half* rn = bp + (nt * 8 + qr) * PITCH_H;
                b0[nt] = *(const unsigned*)rn;
                b1[nt] = *(const unsigned*)(rn + 8);
            }
            #pragma unroll
            for (int mt = 0; mt < 2; ++mt)
                #pragma unroll
                for (int nt = 0; nt < 8; ++nt)
                    mma_f16(*(float4*)acc[mt][nt],
                            a0[mt], a1[mt], a2[mt], a3[mt],
                            b0[nt], b1[nt]);
        }
        stage = (stage + 1 >= NSTAGE) ? 0 : stage + 1;
    }

    const float sc = (bn < scaleCols) ? scale : 1.f;
    #pragma unroll
    for (int nt = 0; nt < 8; ++nt) {
        const int gn = bn + warp_n * 64 + nt * 8 + 2 * t;
        const float2 bz = *(const float2*)&bias[gn];
        #pragma unroll
        for (int mt = 0; mt < 2; ++mt) {
            const int gm = bm + warp_m * 32 + mt * 16 + qr;
            float2 r0, r1;
            r0.x = (acc[mt][nt][0] + bz.x) * sc;
            r0.y = (acc[mt][nt][1] + bz.y) * sc;
            r1.x = (acc[mt][nt][2] + bz.x) * sc;
            r1.y = (acc[mt][nt][3] + bz.y) * sc;
            if (HALF_OUT) {
                __half* Ch = (__half*)Cv;
                *(unsigned*)&Ch[(size_t)gm * N + gn] = h2u(__floats2half2_rn(r0.x, r0.y));
                *(unsigned*)&Ch[(size_t)(gm + 8) * N + gn] = h2u(__floats2half2_rn(r1.x, r1.y));
            } else {
                float* Cf = (float*)Cv;
                *(float2*)&Cf[(size_t)gm * N + gn] = r0;
                *(float2*)&Cf[(size_t)(gm + 8) * N + gn] = r1;
            }
        }
    }
}

// ---------------------------------------------------------------------------
// Neighborhood attention: cp.async fp16 window load, HFMA2 QK, fp32 softmax.
// NEW: normalized weights are spilled once to smem (ws[qi][52], conflict-free
// STS) and the AV loop reads them as float4 (13 LDS.128, quad-broadcast,
// odd-stride conflict-free) -- removes the 49-shfl latency chain.
// ---------------------------------------------------------------------------
#define TQ 8
#define WIN 14
#define KPH 56                        // halfs per k row
#define K_BYTES (196 * 112)           // 21952
#define VPLANE 1576                   // halfs per v plane
#define V_BYTES (4 * VPLANE * 2)      // 12608
#define WSP 52                        // weight row pitch (floats), 13 odd quads
#define WS_BYTES (64 * WSP * 4)       // 13312
#define ATTN_SMEM_BYTES (K_BYTES + V_BYTES + WS_BYTES + 256)   // 48128

__global__ __launch_bounds__(256) void na2d_attn(
    const __half* __restrict__ qkvh, const float* __restrict__ rpb,
    __half* __restrict__ out)
{
    extern __shared__ float sm[];
    __half* ks_h = (__half*)sm;
    __half* vs_h = (__half*)((char*)sm + K_BYTES);
    float*  ws   = (float*)((char*)sm + K_BYTES + V_BYTES);
    float*  rpbs = (float*)((char*)sm + K_BYTES + V_BYTES + WS_BYTES);

    const int b    = blockIdx.z;
    const int head = blockIdx.y;
    const int tY   = blockIdx.x / 7;
    const int tX   = blockIdx.x - tY * 7;
    const int oy   = tY * TQ;
    const int ox   = tX * TQ;
    const int tid  = threadIdx.x;
    const uint32_t smb = smem_u32(sm);

    if (tid < 49) rpbs[tid] = rpb[head * 49 + tid];

    // --- cp.async window load: 196 rows x (4 k-chunks + 4 v-chunks) ---
    const bool interior = (tY >= 1) && (tY <= 5) && (tX >= 1) && (tX <= 5);
    #pragma unroll 1
    for (int idx = tid; idx < 196 * 8; idx += 256) {
        const int row = idx >> 3;
        const int sub = idx & 7;
        const int wy = row / WIN, wx = row - wy * WIN;
        const int gy = oy - PADR + wy, gx = ox - PADR + wx;
        const bool ok = interior || ((unsigned)gy < HH && (unsigned)gx < WW);
        const int kc = sub & 3;
        const uint32_t dst = (sub < 4)
            ? smb + (uint32_t)(row * 112 + kc * 16)
            : smb + (uint32_t)(K_BYTES + kc * (VPLANE * 2) + row * 16);
        const __half* src = ok
            ? qkvh + (size_t)(((b * HH + gy) * WW) + gx) * QKV_N
                   + ((sub < 4) ? 256 : 512) + head * HD + kc * 8
            : qkvh;
        cp16z(dst, src, ok ? 16u : 0u);
    }
    CP_COMMIT();

    // --- q into fp16 registers ---
    const int qi = tid >> 2;
    const int g  = tid & 3;
    const int qy = qi >> 3, qx = qi & 7;
    const size_t qpix = (size_t)((b * HH + oy + qy) * WW) + ox + qx;
    const uint4* qp = (const uint4*)(qkvh + qpix * QKV_N + head * HD);
    uint4 q0 = qp[0], q1 = qp[1], q2 = qp[2], q3 = qp[3];
    unsigned qh[16] = { q0.x, q0.y, q0.z, q0.w, q1.x, q1.y, q1.z, q1.w,
                        q2.x, q2.y, q2.z, q2.w, q3.x, q3.y, q3.z, q3.w };

    CP_WAIT0();
    __syncthreads();

    // --- phase 1: scores via HFMA2 ---
    float sv[13];
    #pragma unroll
    for (int u = 0; u < 13; ++u) {
        const int j = g + 4 * u;
        const bool act = (j < 49);
        const int jc = act ? j : 48;
        const int di = jc / 7, dj = jc - di * 7;
        const int row = (qy + di) * WIN + qx + dj;
        const uint4* kr = (const uint4*)(ks_h + row * KPH);
        const uint4 k0 = kr[0], k1 = kr[1], k2 = kr[2], k3 = kr[3];
        __half2 c0 = __hmul2(u2h(qh[0]),  u2h(k0.x));
        __half2 c1 = __hmul2(u2h(qh[1]),  u2h(k0.y));
        __half2 c2 = __hmul2(u2h(qh[2]),  u2h(k0.z));
        __half2 c3 = __hmul2(u2h(qh[3]),  u2h(k0.w));
        c0 = __hfma2(u2h(qh[4]),  u2h(k1.x), c0);
        c1 = __hfma2(u2h(qh[5]),  u2h(k1.y), c1);
        c2 = __hfma2(u2h(qh[6]),  u2h(k1.z), c2);
        c3 = __hfma2(u2h(qh[7]),  u2h(k1.w), c3);
        c0 = __hfma2(u2h(qh[8]),  u2h(k2.x), c0);
        c1 = __hfma2(u2h(qh[9]),  u2h(k2.y), c1);
        c2 = __hfma2(u2h(qh[10]), u2h(k2.z), c2);
        c3 = __hfma2(u2h(qh[11]), u2h(k2.w), c3);
        c0 = __hfma2(u2h(qh[12]), u2h(k3.x), c0);
        c1 = __hfma2(u2h(qh[13]), u2h(k3.y), c1);
        c2 = __hfma2(u2h(qh[14]), u2h(k3.z), c2);
        c3 = __hfma2(u2h(qh[15]), u2h(k3.w), c3);
        const __half2 r = __hadd2(__hadd2(c0, c1), __hadd2(c2, c3));
        const float2 f = __half22float2(r);
        sv[u] = act ? (f.x + f.y + rpbs[jc]) : -1e30f;
    }

    // --- softmax across quad (fp32) ---
    float m = sv[0];
    #pragma unroll
    for (int u = 1; u < 13; ++u) m = fmaxf(m, sv[u]);
    m = fmaxf(m, __shfl_xor_sync(0xffffffffu, m, 1));
    m = fmaxf(m, __shfl_xor_sync(0xffffffffu, m, 2));
    float ssum = 0.f;
    #pragma unroll
    for (int u = 0; u < 13; ++u) {
        const float e = __expf(sv[u] - m);
        sv[u] = e;
        ssum += e;
    }
    ssum += __shfl_xor_sync(0xffffffffu, ssum, 1);
    ssum += __shfl_xor_sync(0xffffffffu, ssum, 2);
    const float inv = 1.f / ssum;

    // --- spill normalized weights (inactive j>=49 become 0) ---
    float* wsq = ws + qi * WSP;
    #pragma unroll
    for (int u = 0; u < 13; ++u) wsq[g + 4 * u] = sv[u] * inv;
    __syncwarp();

    // --- phase 3: AV with float4 weight loads (no shfl chain) ---
    const __half* vbase = vs_h + g * VPLANE;
    float4 a0 = make_float4(0.f, 0.f, 0.f, 0.f);
    float4 a1 = make_float4(0.f, 0.f, 0.f, 0.f);
    #pragma unroll
    for (int jg = 0; jg < 13; ++jg) {
        const float4 w4 = *(const float4*)(wsq + jg * 4);
        #pragma unroll
        for (int c = 0; c < 4; ++c) {
            const int j = jg * 4 + c;
            if (j < 49) {
                const int di = j / 7, dj = j - di * 7;
                const float w = (c == 0) ? w4.x : (c == 1) ? w4.y
                              : (c == 2) ? w4.z : w4.w;
                const int row = (qy + di) * WIN + qx + dj;
                const uint4 vv = *(const uint4*)(vbase + row * 8);
                const float2 f0 = __half22float2(u2h(vv.x));
                const float2 f1 = __half22float2(u2h(vv.y));
                const float2 f2 = __half22float2(u2h(vv.z));
                const float2 f3 = __half22float2(u2h(vv.w));
                a0.x = fmaf(w, f0.x, a0.x); a0.y = fmaf(w, f0.y, a0.y);
                a0.z = fmaf(w, f1.x, a0.z); a0.w = fmaf(w, f1.y, a0.w);
                a1.x = fmaf(w, f2.x, a1.x); a1.y = fmaf(w, f2.y, a1.y);
                a1.z = fmaf(w, f3.x, a1.z); a1.w = fmaf(w, f3.y, a1.w);
            }
        }
    }
    uint4 o;
    o.x = h2u(__floats2half2_rn(a0.x, a0.y));
    o.y = h2u(__floats2half2_rn(a0.z, a0.w));
    o.z = h2u(__floats2half2_rn(a1.x, a1.y));
    o.w = h2u(__floats2half2_rn(a1.z, a1.w));
    *(uint4*)(out + qpix * CC + head * HD + g * 8) = o;
}

// ---------------------------------------------------------------------------
extern "C" void kernel_launch(void* const* d_in, const int* in_sizes, int n_in,
                              void* d_out, int out_size)
{
    (void)in_sizes; (void)n_in; (void)out_size;
    const float* x      = (const float*)d_in[0];
    const float* w_qkv  = (const float*)d_in[1];
    const float* b_qkv  = (const float*)d_in[2];
    const float* rpb    = (const float*)d_in[3];
    const float* w_proj = (const float*)d_in[4];
    const float* b_proj = (const float*)d_in[5];
    float* out = (float*)d_out;

    __half *qkvh = nullptr, *attnh = nullptr, *xh = nullptr, *wqh = nullptr, *wph = nullptr;
    cudaGetSymbolAddress((void**)&qkvh, g_qkvh);
    cudaGetSymbolAddress((void**)&attnh, g_attnh);
    cudaGetSymbolAddress((void**)&xh, g_xh);
    cudaGetSymbolAddress((void**)&wqh, g_wqh);
    cudaGetSymbolAddress((void**)&wph, g_wph);

    cudaFuncSetAttribute(tgemm_h<true>, cudaFuncAttributeMaxDynamicSharedMemorySize,
                         GEMM_SMEM);
    cudaFuncSetAttribute(tgemm_h<false>, cudaFuncAttributeMaxDynamicSharedMemorySize,
                         GEMM_SMEM);
    cudaFuncSetAttribute(na2d_attn, cudaFuncAttributeMaxDynamicSharedMemorySize,
                         ATTN_SMEM_BYTES);

    const float qscale = 0.17677669529663689f; // 32^-0.5

    // 0) prep: x -> fp16; weights -> transposed [N][K] fp16
    {
        const int nx = M_TOTAL * CC / 4;
        f32_to_f16<<<(nx + 255) / 256, 256>>>((const float4*)x, xh, nx);
        transpose_h<<<dim3(QKV_N / 32, CC / 32), dim3(32, 8)>>>(w_qkv, wqh, CC, QKV_N);
        transpose_h<<<dim3(CC / 32, CC / 32), dim3(32, 8)>>>(w_proj, wph, CC, CC);
    }

    // 1) qkv = x @ w_qkv + b_qkv  (q cols pre-scaled; fp16 output)
    tgemm_h<true><<<dim3(QKV_N / 128, M_TOTAL / 128), 256, GEMM_SMEM>>>(
        xh, wqh, b_qkv, qkvh, QKV_N, 256, qscale);

    // 2) neighborhood attention (all-fp16 I/O)
    na2d_attn<<<dim3(49, NHEAD, BATCH), 256, ATTN_SMEM_BYTES>>>(qkvh, rpb, attnh);

    // 3) out = attn @ w_proj + b_proj (fp32 output)
    tgemm_h<false><<<dim3(CC / 128, M_TOTAL / 128), 256, GEMM_SMEM>>>(
        attnh, wph, b_proj, out, CC, 0, 1.f);
}